// round 3
// baseline (speedup 1.0000x reference)
#include <cuda_runtime.h>
#include <cstdint>

typedef unsigned long long ull;

#define T_STEPS 2048
#define BATCH   64
#define DIN     256
#define HID     256
#define GDIM    1024   // 4*HID gate columns
#define ODIM    128

#define NCHUNK  16     // CTAs per batch group (n-chunks)
#define NGROUP  8      // batch groups
#define BLOC    8      // batch elements per group
#define GCH     64     // permuted gate columns per chunk

// ---------------- static device scratch (no allocation allowed) -------------
__device__ float    g_xproj[(size_t)T_STEPS * BATCH * GDIM];  // 512 MB
__device__ float    g_WdT[GDIM * DIN];    // permuted [g'][d]
__device__ float    g_WhT[GDIM * HID];    // permuted [g'][k]
__device__ float    g_b4[GDIM];
__device__ float    g_h[2][BATCH * HID];  // double-buffered hidden state
__device__ unsigned g_bar[NGROUP];        // per-group barrier counters

// ---------------- helpers ---------------------------------------------------
union F2U { float2 f; ull u; };
__device__ __forceinline__ ull pack2(float x, float y) { F2U t; t.f = make_float2(x, y); return t.u; }
__device__ __forceinline__ float2 unpack2(ull v) { F2U t; t.u = v; return t.f; }

__device__ __forceinline__ void ffma2(ull &acc, ull a, ull b) {
    asm("fma.rn.f32x2 %0, %1, %2, %0;" : "+l"(acc) : "l"(a), "l"(b));
}

__device__ __forceinline__ float sigf(float x) {
    return __fdividef(1.f, 1.f + __expf(-x));
}
__device__ __forceinline__ float tanhfast(float x) {
    return 1.f - __fdividef(2.f, __expf(2.f * x) + 1.f);
}

// ---------------- kernel 0: permute weights, zero barriers ------------------
__global__ void prep_kernel(const float* __restrict__ Wf, const float* __restrict__ Wi,
                            const float* __restrict__ Wc, const float* __restrict__ Wo,
                            const float* __restrict__ bf, const float* __restrict__ bi,
                            const float* __restrict__ bc, const float* __restrict__ bo) {
    int gp = blockIdx.x;          // permuted gate column g' = 4n + gate
    int d  = threadIdx.x;         // 0..255
    int gate = gp & 3, n = gp >> 2;
    const float* W = (gate == 0) ? Wf : (gate == 1) ? Wi : (gate == 2) ? Wc : Wo;
    const float* B = (gate == 0) ? bf : (gate == 1) ? bi : (gate == 2) ? bc : bo;
    g_WdT[gp * DIN + d] = W[n * (DIN + HID) + d];
    g_WhT[gp * HID + d] = W[n * (DIN + HID) + DIN + d];
    if (d == 0) g_b4[gp] = B[n];
    if (gp == 0 && d < NGROUP) g_bar[d] = 0u;
}

// ---------------- kernel 1: x_proj GEMM (f32x2 packed FMA) ------------------
// rows r = t*64 + b ; out[r][g'] = inputs[b,t,:] . WdT[g',:] + b4[g']
__global__ __launch_bounds__(256) void xproj_kernel(const float* __restrict__ inputs) {
    __shared__ float As[32][132];   // [k][r]
    __shared__ float Bs[32][68];    // [k][g]
    int tid   = threadIdx.x;
    int Rbase = blockIdx.x * 128;
    int Gbase = blockIdx.y * 64;
    int tg = tid & 15;              // 4 cols each
    int tr = tid >> 4;              // 8 rows each

    ull acc[4][4];                  // [gi][row-pair]
    #pragma unroll
    for (int gi = 0; gi < 4; gi++)
        #pragma unroll
        for (int rp = 0; rp < 4; rp++) acc[gi][rp] = 0ull;

    for (int k0 = 0; k0 < DIN; k0 += 32) {
        #pragma unroll
        for (int i = 0; i < 4; i++) {            // A tile 128x32
            int s = tid + i * 256;
            int row = s >> 3, d4 = s & 7;
            int r = Rbase + row;
            int b = r & 63, t = r >> 6;
            const float4 v = *(const float4*)&inputs[((size_t)b * T_STEPS + t) * DIN + k0 + d4 * 4];
            As[d4 * 4 + 0][row] = v.x; As[d4 * 4 + 1][row] = v.y;
            As[d4 * 4 + 2][row] = v.z; As[d4 * 4 + 3][row] = v.w;
        }
        #pragma unroll
        for (int i = 0; i < 2; i++) {            // B tile 64x32
            int s = tid + i * 256;
            int gr = s >> 3, d4 = s & 7;
            const float4 v = *(const float4*)&g_WdT[(size_t)(Gbase + gr) * DIN + k0 + d4 * 4];
            Bs[d4 * 4 + 0][gr] = v.x; Bs[d4 * 4 + 1][gr] = v.y;
            Bs[d4 * 4 + 2][gr] = v.z; Bs[d4 * 4 + 3][gr] = v.w;
        }
        __syncthreads();
        #pragma unroll
        for (int k = 0; k < 32; k++) {
            ull ap[4];
            #pragma unroll
            for (int rp = 0; rp < 4; rp++)
                ap[rp] = *(const ull*)&As[k][tr * 8 + rp * 2];
            const float4 bv = *(const float4*)&Bs[k][tg * 4];
            ull bs0 = pack2(bv.x, bv.x), bs1 = pack2(bv.y, bv.y);
            ull bs2 = pack2(bv.z, bv.z), bs3 = pack2(bv.w, bv.w);
            #pragma unroll
            for (int rp = 0; rp < 4; rp++) {
                ffma2(acc[0][rp], ap[rp], bs0);
                ffma2(acc[1][rp], ap[rp], bs1);
                ffma2(acc[2][rp], ap[rp], bs2);
                ffma2(acc[3][rp], ap[rp], bs3);
            }
        }
        __syncthreads();
    }
    int g0 = Gbase + tg * 4;
    float4 bias = *(const float4*)&g_b4[g0];
    #pragma unroll
    for (int rp = 0; rp < 4; rp++) {
        float2 p0 = unpack2(acc[0][rp]), p1 = unpack2(acc[1][rp]);
        float2 p2 = unpack2(acc[2][rp]), p3 = unpack2(acc[3][rp]);
        size_t r0 = (size_t)(Rbase + tr * 8 + rp * 2);
        *(float4*)&g_xproj[r0 * GDIM + g0] =
            make_float4(p0.x + bias.x, p1.x + bias.y, p2.x + bias.z, p3.x + bias.w);
        *(float4*)&g_xproj[(r0 + 1) * GDIM + g0] =
            make_float4(p0.y + bias.x, p1.y + bias.y, p2.y + bias.z, p3.y + bias.w);
    }
}

// ---------------- kernel 2: persistent LSTM scan ----------------------------
// 128 CTAs = 8 batch-groups x 16 n-chunks; per-group L2 barrier each step.
__global__ __launch_bounds__(256) void scan_kernel() {
    __shared__ ull   hsm[BLOC * HID / 2];       // h pairs: [b][kpair]
    __shared__ float partial[8][GCH][9];        // k-chunk partial sums (padded)
    __shared__ ull   xps2[256];                 // x_proj tile (as pairs)
    __shared__ float cs[BLOC * NCHUNK];         // cell state slice (CTA-private)

    int tid = threadIdx.x;
    int cta = blockIdx.x;
    int c   = cta & (NCHUNK - 1);               // n-chunk
    int gb  = cta / NCHUNK;                     // batch group
    int g2  = tid & 31;                         // gate-col lane (2 cols: g2, g2+32)
    int kc  = tid >> 5;                         // k-chunk of 32 (8 chunks)

    // Wh slice -> registers, k-paired for f32x2
    ull wh[2][16];
    #pragma unroll
    for (int gi = 0; gi < 2; gi++) {
        int gp = c * GCH + g2 + gi * 32;
        const float4* src = (const float4*)&g_WhT[(size_t)gp * HID + kc * 32];
        #pragma unroll
        for (int j = 0; j < 8; j++) {
            float4 v = src[j];
            wh[gi][2 * j]     = pack2(v.x, v.y);
            wh[gi][2 * j + 1] = pack2(v.z, v.w);
        }
    }
    // h(0)=0, c(0)=0
    for (int i = tid; i < BLOC * HID / 2; i += 256) hsm[i] = 0ull;
    if (tid < BLOC * NCHUNK) cs[tid] = 0.f;

    // x_proj prefetch: thread covers (bl, 2 gate cols)
    int bl  = tid >> 5;
    int gl2 = (tid & 31) * 2;
    size_t xbase = (size_t)(gb * BLOC + bl) * GDIM + c * GCH + gl2;
    ull xpre = *(const ull*)&g_xproj[xbase];
    __syncthreads();

    unsigned* barp = &g_bar[gb];
    for (int t = 0; t < T_STEPS; t++) {
        // publish x_proj(t); prefetch x_proj(t+1)
        xps2[tid] = xpre;
        if (t + 1 < T_STEPS)
            xpre = *(const ull*)&g_xproj[(size_t)(t + 1) * (BATCH * GDIM) + xbase];

        // recurrent GEMM: 2 gate-cols x 8 batches over 32-k chunk
        ull acc[2][8];
        #pragma unroll
        for (int gi = 0; gi < 2; gi++)
            #pragma unroll
            for (int b = 0; b < 8; b++) acc[gi][b] = 0ull;
        #pragma unroll
        for (int k2 = 0; k2 < 16; k2++) {
            int ka = kc * 16 + k2;
            ull hb[8];
            #pragma unroll
            for (int b = 0; b < 8; b++) hb[b] = hsm[b * (HID / 2) + ka];
            #pragma unroll
            for (int b = 0; b < 8; b++) {
                ffma2(acc[0][b], wh[0][k2], hb[b]);
                ffma2(acc[1][b], wh[1][k2], hb[b]);
            }
        }
        #pragma unroll
        for (int gi = 0; gi < 2; gi++) {
            int gl = g2 + gi * 32;
            #pragma unroll
            for (int b = 0; b < 8; b++) {
                float2 p = unpack2(acc[gi][b]);
                partial[kc][gl][b] = p.x + p.y;
            }
        }
        __syncthreads();

        int wb = (t + 1) & 1;
        // gate reduce + nonlinearity + h_new store (128 threads: b x n)
        if (tid < 128) {
            int b = tid >> 4, n = tid & 15;
            int gl = 4 * n;
            const float* xpsf = (const float*)xps2;
            float v0 = xpsf[b * GCH + gl];
            float v1 = xpsf[b * GCH + gl + 1];
            float v2 = xpsf[b * GCH + gl + 2];
            float v3 = xpsf[b * GCH + gl + 3];
            #pragma unroll
            for (int kk = 0; kk < 8; kk++) {
                v0 += partial[kk][gl][b];
                v1 += partial[kk][gl + 1][b];
                v2 += partial[kk][gl + 2][b];
                v3 += partial[kk][gl + 3][b];
            }
            float f  = sigf(v0);
            float ii = sigf(v1);
            float ch = tanhfast(v2);
            float oo = sigf(v3);
            float cn = f * cs[tid] + ii * ch;
            cs[tid] = cn;
            float hn = oo * tanhfast(cn);
            g_h[wb][(gb * BLOC + b) * HID + c * NCHUNK + n] = hn;
        }
        __threadfence();      // make h stores GPU-visible
        __syncthreads();

        if (tid == 0) {
            asm volatile("red.release.gpu.global.add.u32 [%0], %1;"
                         :: "l"(barp), "r"(1u) : "memory");
            unsigned tgt = (unsigned)(NCHUNK) * (unsigned)(t + 1);
            unsigned v;
            do {
                asm volatile("ld.acquire.gpu.global.u32 %0, [%1];"
                             : "=r"(v) : "l"(barp) : "memory");
            } while (v < tgt);
        }
        __syncthreads();

        // reload full h(t+1) for this group (L2-coherent loads)
        if (t + 1 < T_STEPS) {
            #pragma unroll
            for (int j = 0; j < 4; j++) {
                int idx = tid + j * 256;            // [0,1024): b x 128 pairs
                int b = idx >> 7, p = idx & 127;
                float2 v = __ldcg((const float2*)&g_h[wb][(gb * BLOC + b) * HID + 2 * p]);
                hsm[b * (HID / 2) + p] = pack2(v.x, v.y);
            }
            __syncthreads();
        }
    }
}

// ---------------- kernel 3: output projection -------------------------------
__global__ __launch_bounds__(128) void out_kernel(const float* __restrict__ W_out,
                                                  const float* __restrict__ b_out,
                                                  float* __restrict__ out) {
    __shared__ float h[HID];
    int b = blockIdx.x, o = threadIdx.x;
    const float* hrow = &g_h[T_STEPS & 1][b * HID];
    h[o] = hrow[o];
    h[o + 128] = hrow[o + 128];
    __syncthreads();
    float s = b_out[o];
    const float* w = &W_out[o * HID];
    #pragma unroll 8
    for (int k = 0; k < HID; k++) s += h[k] * w[k];
    out[b * ODIM + o] = s;
}

// ---------------- launch -----------------------------------------------------
extern "C" void kernel_launch(void* const* d_in, const int* in_sizes, int n_in,
                              void* d_out, int out_size) {
    const float* inputs = (const float*)d_in[0];
    const float* W_f = (const float*)d_in[1];
    const float* b_f = (const float*)d_in[2];
    const float* W_i = (const float*)d_in[3];
    const float* b_i = (const float*)d_in[4];
    const float* W_c = (const float*)d_in[5];
    const float* b_c = (const float*)d_in[6];
    const float* W_o = (const float*)d_in[7];
    const float* b_o = (const float*)d_in[8];
    const float* W_out = (const float*)d_in[9];
    const float* b_out = (const float*)d_in[10];
    float* out = (float*)d_out;

    prep_kernel<<<GDIM, 256>>>(W_f, W_i, W_c, W_o, b_f, b_i, b_c, b_o);
    xproj_kernel<<<dim3((T_STEPS * BATCH) / 128, GDIM / 64), 256>>>(inputs);
    scan_kernel<<<NGROUP * NCHUNK, 256>>>();
    out_kernel<<<BATCH, 128>>>(W_out, b_out, out);
}

// round 5
// speedup vs baseline: 1.0090x; 1.0090x over previous
#include <cuda_runtime.h>
#include <cstdint>

typedef unsigned long long ull;

#define T_STEPS 2048
#define BATCH   64
#define DIN     256
#define HID     256
#define GDIM    1024   // 4*HID gate columns
#define ODIM    128

#define NCHUNK  16     // CTAs per batch group (n-chunks)
#define NGROUP  8      // batch groups
#define BLOC    8      // batch elements per group
#define GCH     64     // permuted gate columns per chunk

// ---------------- static device scratch (no allocation allowed) -------------
__device__ float    g_xproj[(size_t)T_STEPS * BATCH * GDIM];  // 512 MB
__device__ float    g_WdT[GDIM * DIN];    // permuted [g'][d]
__device__ float    g_WhT[GDIM * HID];    // permuted [g'][k]
__device__ float    g_b4[GDIM];
__device__ float    g_h[2][BATCH * HID];  // double-buffered hidden state
__device__ unsigned g_bar[NGROUP * 32];   // per-group barrier counters, 128B apart

// ---------------- helpers ---------------------------------------------------
union F2U { float2 f; ull u; };
__device__ __forceinline__ ull pack2(float x, float y) { F2U t; t.f = make_float2(x, y); return t.u; }
__device__ __forceinline__ float2 unpack2(ull v) { F2U t; t.u = v; return t.f; }

__device__ __forceinline__ void ffma2(ull &acc, ull a, ull b) {
    asm("fma.rn.f32x2 %0, %1, %2, %0;" : "+l"(acc) : "l"(a), "l"(b));
}

__device__ __forceinline__ float sigf(float x) {
    return __fdividef(1.f, 1.f + __expf(-x));
}
__device__ __forceinline__ float tanhfast(float x) {
    return 1.f - __fdividef(2.f, __expf(2.f * x) + 1.f);
}

// ---------------- kernel 0: permute weights, zero barriers ------------------
__global__ void prep_kernel(const float* __restrict__ Wf, const float* __restrict__ Wi,
                            const float* __restrict__ Wc, const float* __restrict__ Wo,
                            const float* __restrict__ bf, const float* __restrict__ bi,
                            const float* __restrict__ bc, const float* __restrict__ bo) {
    int gp = blockIdx.x;          // permuted gate column g' = 4n + gate
    int d  = threadIdx.x;         // 0..255
    int gate = gp & 3, n = gp >> 2;
    const float* W = (gate == 0) ? Wf : (gate == 1) ? Wi : (gate == 2) ? Wc : Wo;
    const float* B = (gate == 0) ? bf : (gate == 1) ? bi : (gate == 2) ? bc : bo;
    g_WdT[gp * DIN + d] = W[n * (DIN + HID) + d];
    g_WhT[gp * HID + d] = W[n * (DIN + HID) + DIN + d];
    if (d == 0) g_b4[gp] = B[n];
    if (gp == 0 && d < NGROUP) g_bar[d * 32] = 0u;
}

// ---------------- kernel 1: x_proj GEMM (f32x2 packed FMA) ------------------
// rows r = t*64 + b ; out[r][g'] = inputs[b,t,:] . WdT[g',:] + b4[g']
__global__ __launch_bounds__(256) void xproj_kernel(const float* __restrict__ inputs) {
    __shared__ float As[32][136];   // [k][r]  (136: 16B-aligned rows)
    __shared__ float Bs[32][68];    // [k][g]
    int tid   = threadIdx.x;
    int Rbase = blockIdx.x * 128;
    int Gbase = blockIdx.y * 64;
    int tg = tid & 15;              // 4 cols each
    int tr = tid >> 4;              // 8 rows each

    ull acc[4][4];                  // [gi][row-pair]
    #pragma unroll
    for (int gi = 0; gi < 4; gi++)
        #pragma unroll
        for (int rp = 0; rp < 4; rp++) acc[gi][rp] = 0ull;

    for (int k0 = 0; k0 < DIN; k0 += 32) {
        #pragma unroll
        for (int i = 0; i < 4; i++) {            // A tile 128x32
            int s = tid + i * 256;
            int row = s >> 3, d4 = s & 7;
            int r = Rbase + row;
            int b = r & 63, t = r >> 6;
            const float4 v = *(const float4*)&inputs[((size_t)b * T_STEPS + t) * DIN + k0 + d4 * 4];
            As[d4 * 4 + 0][row] = v.x; As[d4 * 4 + 1][row] = v.y;
            As[d4 * 4 + 2][row] = v.z; As[d4 * 4 + 3][row] = v.w;
        }
        #pragma unroll
        for (int i = 0; i < 2; i++) {            // B tile 64x32
            int s = tid + i * 256;
            int gr = s >> 3, d4 = s & 7;
            const float4 v = *(const float4*)&g_WdT[(size_t)(Gbase + gr) * DIN + k0 + d4 * 4];
            Bs[d4 * 4 + 0][gr] = v.x; Bs[d4 * 4 + 1][gr] = v.y;
            Bs[d4 * 4 + 2][gr] = v.z; Bs[d4 * 4 + 3][gr] = v.w;
        }
        __syncthreads();
        #pragma unroll
        for (int k = 0; k < 32; k++) {
            ulonglong2 a01 = *(const ulonglong2*)&As[k][tr * 8];
            ulonglong2 a23 = *(const ulonglong2*)&As[k][tr * 8 + 4];
            ull ap[4] = { a01.x, a01.y, a23.x, a23.y };
            const float4 bv = *(const float4*)&Bs[k][tg * 4];
            ull bs0 = pack2(bv.x, bv.x), bs1 = pack2(bv.y, bv.y);
            ull bs2 = pack2(bv.z, bv.z), bs3 = pack2(bv.w, bv.w);
            #pragma unroll
            for (int rp = 0; rp < 4; rp++) {
                ffma2(acc[0][rp], ap[rp], bs0);
                ffma2(acc[1][rp], ap[rp], bs1);
                ffma2(acc[2][rp], ap[rp], bs2);
                ffma2(acc[3][rp], ap[rp], bs3);
            }
        }
        __syncthreads();
    }
    int g0 = Gbase + tg * 4;
    float4 bias = *(const float4*)&g_b4[g0];
    #pragma unroll
    for (int rp = 0; rp < 4; rp++) {
        float2 p0 = unpack2(acc[0][rp]), p1 = unpack2(acc[1][rp]);
        float2 p2 = unpack2(acc[2][rp]), p3 = unpack2(acc[3][rp]);
        size_t r0 = (size_t)(Rbase + tr * 8 + rp * 2);
        *(float4*)&g_xproj[r0 * GDIM + g0] =
            make_float4(p0.x + bias.x, p1.x + bias.y, p2.x + bias.z, p3.x + bias.w);
        *(float4*)&g_xproj[(r0 + 1) * GDIM + g0] =
            make_float4(p0.y + bias.x, p1.y + bias.y, p2.y + bias.z, p3.y + bias.w);
    }
}

// ---------------- kernel 2: persistent LSTM scan ----------------------------
// 128 CTAs = 8 batch-groups x 16 n-chunks; per-group L2 barrier each step.
__global__ __launch_bounds__(256) void scan_kernel() {
    __shared__ __align__(16) ull hsm[BLOC * HID / 2];   // h pairs: [b][kpair]
    __shared__ float partial[8][BLOC][68];              // [kc][b][g] k-partials
    __shared__ __align__(16) ull xps2[256];             // x_proj tile (pairs)
    __shared__ float cs[BLOC * NCHUNK];                 // cell slice (CTA-private)

    int tid = threadIdx.x;
    int cta = blockIdx.x;
    int c   = cta & (NCHUNK - 1);               // n-chunk
    int gb  = cta / NCHUNK;                     // batch group
    int g2  = tid & 31;                         // gate-col lane (cols g2, g2+32)
    int kc  = tid >> 5;                         // k-chunk of 32 (8 chunks)

    // Wh slice -> registers, k-paired for f32x2
    ull wh[2][16];
    #pragma unroll
    for (int gi = 0; gi < 2; gi++) {
        int gp = c * GCH + g2 + gi * 32;
        const float4* src = (const float4*)&g_WhT[(size_t)gp * HID + kc * 32];
        #pragma unroll
        for (int j = 0; j < 8; j++) {
            float4 v = src[j];
            wh[gi][2 * j]     = pack2(v.x, v.y);
            wh[gi][2 * j + 1] = pack2(v.z, v.w);
        }
    }
    // h(0)=0, c(0)=0
    for (int i = tid; i < BLOC * HID / 2; i += 256) hsm[i] = 0ull;
    if (tid < BLOC * NCHUNK) cs[tid] = 0.f;

    // x_proj prefetch: thread covers (bl, 2 gate cols)
    int bl  = tid >> 5;
    int gl2 = (tid & 31) * 2;
    size_t xbase = (size_t)(gb * BLOC + bl) * GDIM + c * GCH + gl2;
    ull xpre = *(const ull*)&g_xproj[xbase];
    __syncthreads();

    unsigned* barp = &g_bar[gb * 32];
    for (int t = 0; t < T_STEPS; t++) {
        // publish x_proj(t); prefetch x_proj(t+1)
        xps2[tid] = xpre;
        if (t + 1 < T_STEPS)
            xpre = *(const ull*)&g_xproj[(size_t)(t + 1) * (BATCH * GDIM) + xbase];

        // recurrent GEMM: 2 gate-cols x 8 batches over 32-k chunk
        ull acc[2][8];
        #pragma unroll
        for (int gi = 0; gi < 2; gi++)
            #pragma unroll
            for (int b = 0; b < 8; b++) acc[gi][b] = 0ull;
        #pragma unroll
        for (int k4 = 0; k4 < 8; k4++) {                 // 2 k-pairs per iter
            int ka = kc * 16 + k4 * 2;
            ulonglong2 hb[8];
            #pragma unroll
            for (int b = 0; b < 8; b++)
                hb[b] = *(const ulonglong2*)&hsm[b * (HID / 2) + ka];
            #pragma unroll
            for (int b = 0; b < 8; b++) {
                ffma2(acc[0][b], wh[0][2 * k4],     hb[b].x);
                ffma2(acc[1][b], wh[1][2 * k4],     hb[b].x);
                ffma2(acc[0][b], wh[0][2 * k4 + 1], hb[b].y);
                ffma2(acc[1][b], wh[1][2 * k4 + 1], hb[b].y);
            }
        }
        #pragma unroll
        for (int gi = 0; gi < 2; gi++) {
            int gl = g2 + gi * 32;
            #pragma unroll
            for (int b = 0; b < 8; b++) {
                float2 p = unpack2(acc[gi][b]);
                partial[kc][b][gl] = p.x + p.y;
            }
        }
        __syncthreads();

        int wb = (t + 1) & 1;
        // gate reduce + nonlinearity + h_new store (128 threads: b x n)
        if (tid < 128) {
            int b = tid >> 4, n = tid & 15;
            int gl = 4 * n;
            float4 v = *(const float4*)&((const float*)xps2)[b * GCH + gl];
            #pragma unroll
            for (int kk = 0; kk < 8; kk++) {
                float4 p = *(const float4*)&partial[kk][b][gl];
                v.x += p.x; v.y += p.y; v.z += p.z; v.w += p.w;
            }
            float f  = sigf(v.x);
            float ii = sigf(v.y);
            float ch = tanhfast(v.z);
            float oo = sigf(v.w);
            float cn = f * cs[tid] + ii * ch;
            cs[tid] = cn;
            float hn = oo * tanhfast(cn);
            g_h[wb][(gb * BLOC + b) * HID + c * NCHUNK + n] = hn;
        }
        __syncthreads();   // all h stores program-ordered before tid0's release

        if (tid == 0) {
            asm volatile("red.release.gpu.global.add.u32 [%0], %1;"
                         :: "l"(barp), "r"(1u) : "memory");
            unsigned tgt = (unsigned)(NCHUNK) * (unsigned)(t + 1);
            unsigned v;
            do {
                asm volatile("ld.acquire.gpu.global.u32 %0, [%1];"
                             : "=r"(v) : "l"(barp) : "memory");
            } while (v < tgt);
        }
        __syncthreads();

        // reload full h(t+1) for this group (L2-coherent vector loads)
        if (t + 1 < T_STEPS) {
            #pragma unroll
            for (int j = 0; j < 2; j++) {
                int idx = tid + j * 256;            // [0,512): b x 64 quads
                int b = idx >> 6, q = idx & 63;
                float4 v = __ldcg((const float4*)&g_h[wb][(gb * BLOC + b) * HID + 4 * q]);
                ((ulonglong2*)hsm)[b * 64 + q] =
                    make_ulonglong2(pack2(v.x, v.y), pack2(v.z, v.w));
            }
            __syncthreads();
        }
    }
}

// ---------------- kernel 3: output projection -------------------------------
__global__ __launch_bounds__(128) void out_kernel(const float* __restrict__ W_out,
                                                  const float* __restrict__ b_out,
                                                  float* __restrict__ out) {
    __shared__ float h[HID];
    int b = blockIdx.x, o = threadIdx.x;
    const float* hrow = &g_h[T_STEPS & 1][b * HID];
    h[o] = hrow[o];
    h[o + 128] = hrow[o + 128];
    __syncthreads();
    float s = b_out[o];
    const float* w = &W_out[o * HID];
    #pragma unroll 8
    for (int k = 0; k < HID; k++) s += h[k] * w[k];
    out[b * ODIM + o] = s;
}

// ---------------- launch -----------------------------------------------------
extern "C" void kernel_launch(void* const* d_in, const int* in_sizes, int n_in,
                              void* d_out, int out_size) {
    const float* inputs = (const float*)d_in[0];
    const float* W_f = (const float*)d_in[1];
    const float* b_f = (const float*)d_in[2];
    const float* W_i = (const float*)d_in[3];
    const float* b_i = (const float*)d_in[4];
    const float* W_c = (const float*)d_in[5];
    const float* b_c = (const float*)d_in[6];
    const float* W_o = (const float*)d_in[7];
    const float* b_o = (const float*)d_in[8];
    const float* W_out = (const float*)d_in[9];
    const float* b_out = (const float*)d_in[10];
    float* out = (float*)d_out;

    prep_kernel<<<GDIM, 256>>>(W_f, W_i, W_c, W_o, b_f, b_i, b_c, b_o);
    xproj_kernel<<<dim3((T_STEPS * BATCH) / 128, GDIM / 64), 256>>>(inputs);
    scan_kernel<<<NGROUP * NCHUNK, 256>>>();
    out_kernel<<<BATCH, 128>>>(W_out, b_out, out);
}